// round 6
// baseline (speedup 1.0000x reference)
#include <cuda_runtime.h>

// ConstrainNet residual:
//   out[0:64]            = V[0,:64] - x0
//   out[t*64 : t*64+64]  = [A B] @ V[t-1] - V[t,:64]   for t = 1..T-1
// Shapes: A (64,64), B (64,32), x0 (64), net_input = V (T=128, 96), out (T*64,)
//
// One timestep per CTA (BT=1): 128 CTAs x 128 threads -> 128 SMs in a single
// wave, 1 warp per SMSP, minimal per-SM serialization. thread = (s, kh):
// s = output row, kh = k-half of the 96-wide dot. 12 LDG.128 stage the AB
// row segment into registers; 48 FMAs into 8 accumulators (24-cycle chain);
// one shfl_xor(1) combines the halves. No smem, no barriers.

constexpr int NS = 64;
constexpr int NA = 96;
constexpr int T  = 128;
constexpr int THREADS = 128;   // 64 rows * 2 k-halves

__global__ __launch_bounds__(THREADS, 1)
void constrainnet_kernel(const float* __restrict__ A,
                         const float* __restrict__ B,
                         const float* __restrict__ x0,
                         const float* __restrict__ V,
                         float* __restrict__ out) {
    const unsigned tid = threadIdx.x;
    const unsigned s   = tid >> 1;     // output row
    const unsigned kh  = tid & 1;      // k-half
    const int t = (int)blockIdx.x;

    // Loads gating the final subtract: issue immediately.
    const float vts = __ldg(&V[t * NA + s]);
    const float x0s = (t == 0) ? __ldg(&x0[s]) : 0.0f;

    // AB row s, k-segment [kh*48, kh*48+48):
    //   kh=0: A[s][0:16) | A[s][16:48)
    //   kh=1: A[s][48:64) | B[s][0:32)
    const float4* X4 = reinterpret_cast<const float4*>(A + s * 64 + kh * 48);
    const float4* Y4 = kh ? reinterpret_cast<const float4*>(B + s * 32)
                          : reinterpret_cast<const float4*>(A + s * 64 + 16);

    const int tprev = (t > 0) ? (t - 1) : 0;   // clamped; t==0 overridden
    const float4* V4 = reinterpret_cast<const float4*>(V + tprev * NA + kh * 48);

    float4 ab[12];
    #pragma unroll
    for (int j = 0; j < 4; ++j) ab[j] = X4[j];
    #pragma unroll
    for (int j = 0; j < 8; ++j) ab[4 + j] = Y4[j];

    // 48 FMAs, 8 independent accumulator chains (6 deep each).
    float a0 = 0.f, a1 = 0.f, a2 = 0.f, a3 = 0.f;
    float b0 = 0.f, b1 = 0.f, b2 = 0.f, b3 = 0.f;
    #pragma unroll
    for (int j = 0; j < 12; j += 2) {
        float4 v0 = V4[j];
        float4 v1 = V4[j + 1];
        a0 = fmaf(ab[j].x, v0.x, a0);
        a1 = fmaf(ab[j].y, v0.y, a1);
        a2 = fmaf(ab[j].z, v0.z, a2);
        a3 = fmaf(ab[j].w, v0.w, a3);
        b0 = fmaf(ab[j + 1].x, v1.x, b0);
        b1 = fmaf(ab[j + 1].y, v1.y, b1);
        b2 = fmaf(ab[j + 1].z, v1.z, b2);
        b3 = fmaf(ab[j + 1].w, v1.w, b3);
    }
    float dot = ((a0 + b0) + (a1 + b1)) + ((a2 + b2) + (a3 + b3));
    dot += __shfl_xor_sync(0xFFFFFFFFu, dot, 1);

    float r = (t == 0) ? (vts - x0s) : (dot - vts);

    if (kh == 0) out[t * NS + s] = r;
}

extern "C" void kernel_launch(void* const* d_in, const int* in_sizes, int n_in,
                              void* d_out, int out_size) {
    const float* A  = (const float*)d_in[0];
    const float* B  = (const float*)d_in[1];
    const float* x0 = (const float*)d_in[2];
    const float* V  = (const float*)d_in[3];
    float* out = (float*)d_out;

    constrainnet_kernel<<<T, THREADS>>>(A, B, x0, V, out);
}

// round 10
// speedup vs baseline: 1.0750x; 1.0750x over previous
#include <cuda_runtime.h>

// ConstrainNet residual:
//   out[0:64]            = V[0,:64] - x0
//   out[t*64 : t*64+64]  = [A B] @ V[t-1] - V[t,:64]   for t = 1..T-1
// Shapes: A (64,64), B (64,32), x0 (64), net_input = V (T=128, 96), out (T*64,)
//
// 64 CTAs x 128 threads, thread = (s, kh). Each thread stages its 48-float
// AB row segment ONCE (12 LDG.128) and reuses it for BOTH timesteps of the
// block (t0, t0+1): two independent 48-FMA/4-acc chains (ILP 2), one
// shfl_xor(1) each to combine k-halves. No smem, no barriers. Gating loads
// (V[t][s], x0) issue first.

constexpr int NS = 64;
constexpr int NA = 96;
constexpr int T  = 128;
constexpr int BT = 2;
constexpr int THREADS = 128;   // 64 rows * 2 k-halves

__global__ __launch_bounds__(THREADS, 1)
void constrainnet_kernel(const float* __restrict__ A,
                         const float* __restrict__ B,
                         const float* __restrict__ x0,
                         const float* __restrict__ V,
                         float* __restrict__ out) {
    const unsigned tid = threadIdx.x;
    const unsigned s   = tid >> 1;     // output row
    const unsigned kh  = tid & 1;      // k-half
    const int t0 = (int)(blockIdx.x * BT);
    const int t1 = t0 + 1;

    // Loads gating the final subtracts: issue immediately.
    const float vt0s = __ldg(&V[t0 * NA + s]);
    const float vt1s = __ldg(&V[t1 * NA + s]);
    const float x0s  = (t0 == 0) ? __ldg(&x0[s]) : 0.0f;

    // AB row s, k-segment [kh*48, kh*48+48):
    //   kh=0: A[s][0:16) | A[s][16:48)
    //   kh=1: A[s][48:64) | B[s][0:32)
    const float4* X4 = reinterpret_cast<const float4*>(A + s * 64 + kh * 48);
    const float4* Y4 = kh ? reinterpret_cast<const float4*>(B + s * 32)
                          : reinterpret_cast<const float4*>(A + s * 64 + 16);

    const int tp0 = (t0 > 0) ? (t0 - 1) : 0;   // clamped; t0==0 overridden
    const float4* Vp0 = reinterpret_cast<const float4*>(V + tp0 * NA + kh * 48);
    const float4* Vp1 = reinterpret_cast<const float4*>(V + t0  * NA + kh * 48);

    // Stage AB segment once (12 independent 128-bit loads).
    float4 ab[12];
    #pragma unroll
    for (int j = 0; j < 4; ++j) ab[j] = X4[j];
    #pragma unroll
    for (int j = 0; j < 8; ++j) ab[4 + j] = Y4[j];

    // Two independent 48-FMA dot products sharing the staged AB registers.
    float a0 = 0.f, a1 = 0.f, a2 = 0.f, a3 = 0.f;   // for t0
    float c0 = 0.f, c1 = 0.f, c2 = 0.f, c3 = 0.f;   // for t1
    #pragma unroll
    for (int j = 0; j < 12; ++j) {
        float4 u = Vp0[j];
        float4 w = Vp1[j];
        a0 = fmaf(ab[j].x, u.x, a0);
        a1 = fmaf(ab[j].y, u.y, a1);
        a2 = fmaf(ab[j].z, u.z, a2);
        a3 = fmaf(ab[j].w, u.w, a3);
        c0 = fmaf(ab[j].x, w.x, c0);
        c1 = fmaf(ab[j].y, w.y, c1);
        c2 = fmaf(ab[j].z, w.z, c2);
        c3 = fmaf(ab[j].w, w.w, c3);
    }
    float dot0 = (a0 + a1) + (a2 + a3);
    float dot1 = (c0 + c1) + (c2 + c3);
    dot0 += __shfl_xor_sync(0xFFFFFFFFu, dot0, 1);
    dot1 += __shfl_xor_sync(0xFFFFFFFFu, dot1, 1);

    const float r0 = (t0 == 0) ? (vt0s - x0s) : (dot0 - vt0s);
    const float r1 = dot1 - vt1s;

    if (kh == 0) {
        out[t0 * NS + s] = r0;
        out[t1 * NS + s] = r1;
    }
}

extern "C" void kernel_launch(void* const* d_in, const int* in_sizes, int n_in,
                              void* d_out, int out_size) {
    const float* A  = (const float*)d_in[0];
    const float* B  = (const float*)d_in[1];
    const float* x0 = (const float*)d_in[2];
    const float* V  = (const float*)d_in[3];
    float* out = (float*)d_out;

    constrainnet_kernel<<<T / BT, THREADS>>>(A, B, x0, V, out);
}